// round 15
// baseline (speedup 1.0000x reference)
#include <cuda_runtime.h>
#include <cstdint>

#define NL 50
#define ND 64
#define NROWS 50000
#define TOTROWS 100000

// 1 / sum_{m=0}^{49} e^{-m}
#define INV_C 0.63212055882855767841f

__device__ float g_H[(size_t)TOTROWS * ND];    // attention output scratch (25.6 MB)
__device__ float g_S[(size_t)TOTROWS * ND];    // te-dot scratch S[row][k] (25.6 MB)
__device__ float g_teT[2 * ND * ND];           // padded transposed te tables

// ------------------------------------------------------------------
// K-1: transpose te tables into padded [k][j] layout (j>=50 -> 0).
// ------------------------------------------------------------------
__global__ void te_transpose_kernel(const float* __restrict__ u_te,
                                    const float* __restrict__ i_te)
{
    const float* te = blockIdx.x ? i_te : u_te;
    float* out = g_teT + blockIdx.x * ND * ND;
    for (int idx = threadIdx.x; idx < ND * ND; idx += 128) {
        int k = idx >> 6, j = idx & 63;
        out[idx] = (j < NL) ? te[j * ND + k] : 0.f;
    }
}

#define HTS 130

// ------------------------------------------------------------------
// K0: S = dst_h @ te^T  (one side per launch).
// ------------------------------------------------------------------
__global__ __launch_bounds__(128) void te_dot_kernel(
    const int side,
    const float* __restrict__ user_h, const float* __restrict__ item_h)
{
    __shared__ __align__(16) float4 sW[ND * 16];    // 16 KB te_T
    __shared__ __align__(16) float sHT[ND * HTS];   // 33.3 KB k-major

    const float* src = side ? item_h : user_h;
    const int t = threadIdx.x;
    const int rp = t & 63, hf = t >> 6;

    for (int i = t; i < ND * 16; i += 128)
        sW[i] = ((const float4*)(g_teT + side * ND * ND))[i];

    const int base = blockIdx.x * 128;
    const int rows = min(128, NROWS - base);
    const float* Hbase = src + (size_t)base * ND;

    for (int i = 0; i < 64; i++) {
        int e = i * 128 + t;
        int rr = e >> 6, k = e & 63;
        sHT[k * HTS + rr] = (rr < rows) ? Hbase[e] : 0.f;
    }
    __syncthreads();

    const ulonglong2* Wp = (const ulonglong2*)sW;
    const int wbase = 8 * hf;
    const int cbase = 32 * hf;
    const int r2 = 2 * rp;

    unsigned long long a0[16], a1[16];
#pragma unroll
    for (int j = 0; j < 16; j++) { a0[j] = 0ull; a1[j] = 0ull; }
#pragma unroll 8
    for (int k = 0; k < ND; k++) {
        float2 h2 = *(const float2*)&sHT[k * HTS + r2];
        unsigned long long h0, h1;
        asm("mov.b64 %0, {%1, %1};" : "=l"(h0) : "f"(h2.x));
        asm("mov.b64 %0, {%1, %1};" : "=l"(h1) : "f"(h2.y));
#pragma unroll
        for (int m = 0; m < 8; m++) {
            ulonglong2 w = Wp[k * 16 + wbase + m];
            asm("fma.rn.f32x2 %0, %1, %2, %0;" : "+l"(a0[2 * m])     : "l"(h0), "l"(w.x));
            asm("fma.rn.f32x2 %0, %1, %2, %0;" : "+l"(a0[2 * m + 1]) : "l"(h0), "l"(w.y));
            asm("fma.rn.f32x2 %0, %1, %2, %0;" : "+l"(a1[2 * m])     : "l"(h1), "l"(w.x));
            asm("fma.rn.f32x2 %0, %1, %2, %0;" : "+l"(a1[2 * m + 1]) : "l"(h1), "l"(w.y));
        }
    }
    __syncthreads();

#pragma unroll
    for (int j = 0; j < 16; j++) {
        float x0, y0, x1, y1;
        asm("mov.b64 {%0, %1}, %2;" : "=f"(x0), "=f"(y0) : "l"(a0[j]));
        asm("mov.b64 {%0, %1}, %2;" : "=f"(x1), "=f"(y1) : "l"(a1[j]));
        *(float2*)&sHT[(cbase + 2 * j) * HTS + r2]     = make_float2(x0, x1);
        *(float2*)&sHT[(cbase + 2 * j + 1) * HTS + r2] = make_float2(y0, y1);
    }
    __syncthreads();

    float* Sbase = g_S + ((size_t)side * NROWS + base) * ND;
    for (int i = 0; i < 64; i++) {
        int e = i * 128 + t;
        int rr = e >> 6, k = e & 63;
        if (rr < rows) Sbase[e] = sHT[k * HTS + rr];
    }
}

// ------------------------------------------------------------------
// attn (one side per launch): one 64-thread block per destination row.
// ------------------------------------------------------------------
__global__ __launch_bounds__(64) void attn_kernel(
    const int side,
    const float* __restrict__ user_h, const float* __restrict__ item_h,
    const int* __restrict__ u_nbr, const int* __restrict__ u_tim,
    const int* __restrict__ i_nbr, const int* __restrict__ i_tim)
{
    __shared__ __align__(16) int   s_tim[52];
    __shared__ __align__(16) int   s_idx[52];
    __shared__ __align__(16) int   s_srt[52];
    __shared__ __align__(16) float s_pd[NL * 4];   // quad partials of <nbr,dst>
    __shared__ __align__(16) float s_S[52];
    __shared__ __align__(16) float s_g[52];
    __shared__ __align__(16) float s_alpha[52];
    __shared__             float s_wsum[2];
    __shared__ __align__(16) float4 s_red[32];

    const int n = blockIdx.x;
    const size_t grow = (size_t)side * NROWS + n;
    const int t = threadIdx.x;
    const int lane = t & 31, wid = t >> 5;
    const int g = t >> 4, c = t & 15;
    const bool uside = (side == 0);
    const float*  dst  = (uside ? user_h : item_h) + (size_t)n * ND;
    const float4* src4 = (const float4*)(uside ? item_h : user_h);
    const int* nbr = (uside ? u_nbr : i_nbr) + (size_t)n * NL;
    const int* tim = (uside ? u_tim : i_tim) + (size_t)n * NL;
    const float* Srow = g_S + grow * ND;

    const float4 dstc = __ldg(&((const float4*)dst)[c]);

    if (t < NL) {
        s_idx[t] = __ldg(nbr + t);
        s_tim[t] = __ldg(tim + t);
        s_S[t]   = __ldg(Srow + t);
    } else if (t < 52) {
        s_tim[t]   = 0x7fffffff;   // pad: strictly greater, no ties
        s_idx[t]   = 0;
        s_g[t]     = -1e30f;       // pad for max loop
        s_alpha[t] = 0.f;          // pad for pass C
    }
    __syncthreads();               // bar1

    // --- gather: 16 consecutive lanes fetch one 256B neighbor row ---
    float4 v[13];
#pragma unroll
    for (int i = 0; i < 13; i++) {
        const int l = 4 * i + g;
        if (l < NL)
            v[i] = __ldg(&src4[(size_t)s_idx[l] * 16 + c]);
        else
            v[i] = make_float4(0.f, 0.f, 0.f, 0.f);
    }

    // --- rank / srt (stable argsort) while gather is in flight ---
    int ro = 0;
    if (t < NL) {
        const int tl = s_tim[t];
        int r = 0;
#pragma unroll
        for (int i = 0; i < 13; i++) {
            int4 w = ((const int4*)s_tim)[i];
            int j = 4 * i;
            r += (w.x < tl) | ((w.x == tl) & (j     < t));
            r += (w.y < tl) | ((w.y == tl) & (j + 1 < t));
            r += (w.z < tl) | ((w.z == tl) & (j + 2 < t));
            r += (w.w < tl) | ((w.w == tl) & (j + 3 < t));
        }
        s_srt[r] = t;
        ro = NL - 1 - r;
    }

    // --- score dots: 2 shfl levels -> quad partials -> smem ---
#pragma unroll
    for (int i = 0; i < 13; i++) {
        const int l = 4 * i + g;
        float d = v[i].x * dstc.x + v[i].y * dstc.y + v[i].z * dstc.z + v[i].w * dstc.w;
        d += __shfl_xor_sync(0xffffffffu, d, 1);
        d += __shfl_xor_sync(0xffffffffu, d, 2);
        if (((c & 3) == 0) && l < NL)
            s_pd[l * 4 + (c >> 2)] = d;
    }
    __syncthreads();   // bar2: partials + s_srt visible

    // --- e, rank prior, g ---
    if (t < NL) {
        float4 pd = ((const float4*)s_pd)[t];
        float dsum = (pd.x + pd.y) + (pd.z + pd.w);
        float e = (dsum + s_S[ro]) * 6.25f;                 // L/sqrt(D)
        float p = __expf((float)s_srt[t] - 49.0f) * INV_C;  // softmax of permutation
        s_g[t] = e * p;
    }
    __syncthreads();   // bar3

    // --- softmax max (redundant per-thread, ILP-friendly) ---
    float mx = -1e30f;
#pragma unroll
    for (int i = 0; i < 13; i++) {
        float4 g4 = ((const float4*)s_g)[i];
        mx = fmaxf(mx, fmaxf(fmaxf(g4.x, g4.y), fmaxf(g4.z, g4.w)));
    }
    if (t < NL) s_alpha[t] = __expf(s_g[t] - mx);
    __syncthreads();   // bar4

    // --- pass C: weighted column sums + folded alpha sum ---
    float4 pc = make_float4(0.f, 0.f, 0.f, 0.f);
    float psum = 0.f;
#pragma unroll
    for (int i = 0; i < 13; i++) {
        const float a = s_alpha[4 * i + g];   // pad zeros kill l>=50
        psum += a;
        pc.x += a * v[i].x; pc.y += a * v[i].y;
        pc.z += a * v[i].z; pc.w += a * v[i].w;
    }
    pc.x += __shfl_xor_sync(0xffffffffu, pc.x, 16);
    pc.y += __shfl_xor_sync(0xffffffffu, pc.y, 16);
    pc.z += __shfl_xor_sync(0xffffffffu, pc.z, 16);
    pc.w += __shfl_xor_sync(0xffffffffu, pc.w, 16);
    psum += __shfl_xor_sync(0xffffffffu, psum, 16);
    if (lane < 16) s_red[wid * 16 + c] = pc;
    if (lane == 0) s_wsum[wid] = psum;
    __syncthreads();   // bar5

    if (t < 16) {
        const float inv = 1.0f / (s_wsum[0] + s_wsum[1]);
        float4 a = s_red[t], b = s_red[16 + t];
        float4 h;
        h.x = (a.x + b.x) * inv;
        h.y = (a.y + b.y) * inv;
        h.z = (a.z + b.z) * inv;
        h.w = (a.w + b.w) * inv;
        ((float4*)(g_H + grow * ND))[t] = h;
    }
}

// ------------------------------------------------------------------
// mlp (one side per launch): out = relu(H@W1+b1)@W2+b2
// ------------------------------------------------------------------
__global__ __launch_bounds__(128) void mlp_kernel(
    const int side,
    const float* __restrict__ W1, const float* __restrict__ b1,
    const float* __restrict__ W2, const float* __restrict__ b2,
    float* __restrict__ out)
{
    __shared__ __align__(16) float4 sW[ND * 16];    // 16 KB, W1 then W2
    __shared__ float sb1[ND];
    __shared__ float sb2[ND];
    __shared__ __align__(16) float sHT[ND * HTS];   // 33.3 KB, k-major

    const int t = threadIdx.x;
    const int rp = t & 63, hf = t >> 6;

    for (int i = t; i < ND * 16; i += 128)
        sW[i] = ((const float4*)W1)[i];
    if (t < ND) { sb1[t] = b1[t]; sb2[t] = b2[t]; }

    const int base = blockIdx.x * 128;
    const int rows = min(128, NROWS - base);
    const float* Hbase = g_H + ((size_t)side * NROWS + base) * ND;

    for (int i = 0; i < 64; i++) {
        int e = i * 128 + t;
        int rr = e >> 6, k = e & 63;
        sHT[k * HTS + rr] = (rr < rows) ? Hbase[e] : 0.f;
    }
    __syncthreads();

    const ulonglong2* Wp = (const ulonglong2*)sW;
    const int wbase = 8 * hf;
    const int cbase = 32 * hf;
    const int r2 = 2 * rp;

    // ---- layer 1 ----
    unsigned long long a0[16], a1[16];
#pragma unroll
    for (int j = 0; j < 16; j++) {
        unsigned long long b;
        asm("mov.b64 %0, {%1, %2};" : "=l"(b)
            : "f"(sb1[cbase + 2 * j]), "f"(sb1[cbase + 2 * j + 1]));
        a0[j] = b; a1[j] = b;
    }
#pragma unroll 8
    for (int k = 0; k < ND; k++) {
        float2 h2 = *(const float2*)&sHT[k * HTS + r2];
        unsigned long long h0, h1;
        asm("mov.b64 %0, {%1, %1};" : "=l"(h0) : "f"(h2.x));
        asm("mov.b64 %0, {%1, %1};" : "=l"(h1) : "f"(h2.y));
#pragma unroll
        for (int m = 0; m < 8; m++) {
            ulonglong2 w = Wp[k * 16 + wbase + m];
            asm("fma.rn.f32x2 %0, %1, %2, %0;" : "+l"(a0[2 * m])     : "l"(h0), "l"(w.x));
            asm("fma.rn.f32x2 %0, %1, %2, %0;" : "+l"(a0[2 * m + 1]) : "l"(h0), "l"(w.y));
            asm("fma.rn.f32x2 %0, %1, %2, %0;" : "+l"(a1[2 * m])     : "l"(h1), "l"(w.x));
            asm("fma.rn.f32x2 %0, %1, %2, %0;" : "+l"(a1[2 * m + 1]) : "l"(h1), "l"(w.y));
        }
    }
    __syncthreads();

#pragma unroll
    for (int j = 0; j < 16; j++) {
        float x0, y0, x1, y1;
        asm("mov.b64 {%0, %1}, %2;" : "=f"(x0), "=f"(y0) : "l"(a0[j]));
        asm("mov.b64 {%0, %1}, %2;" : "=f"(x1), "=f"(y1) : "l"(a1[j]));
        *(float2*)&sHT[(cbase + 2 * j) * HTS + r2] =
            make_float2(fmaxf(x0, 0.f), fmaxf(x1, 0.f));
        *(float2*)&sHT[(cbase + 2 * j + 1) * HTS + r2] =
            make_float2(fmaxf(y0, 0.f), fmaxf(y1, 0.f));
    }

    for (int i = t; i < ND * 16; i += 128)
        sW[i] = ((const float4*)W2)[i];
    __syncthreads();

    // ---- layer 2 ----
#pragma unroll
    for (int j = 0; j < 16; j++) {
        unsigned long long b;
        asm("mov.b64 %0, {%1, %2};" : "=l"(b)
            : "f"(sb2[cbase + 2 * j]), "f"(sb2[cbase + 2 * j + 1]));
        a0[j] = b; a1[j] = b;
    }
#pragma unroll 8
    for (int k = 0; k < ND; k++) {
        float2 h2 = *(const float2*)&sHT[k * HTS + r2];
        unsigned long long h0, h1;
        asm("mov.b64 %0, {%1, %1};" : "=l"(h0) : "f"(h2.x));
        asm("mov.b64 %0, {%1, %1};" : "=l"(h1) : "f"(h2.y));
#pragma unroll
        for (int m = 0; m < 8; m++) {
            ulonglong2 w = Wp[k * 16 + wbase + m];
            asm("fma.rn.f32x2 %0, %1, %2, %0;" : "+l"(a0[2 * m])     : "l"(h0), "l"(w.x));
            asm("fma.rn.f32x2 %0, %1, %2, %0;" : "+l"(a0[2 * m + 1]) : "l"(h0), "l"(w.y));
            asm("fma.rn.f32x2 %0, %1, %2, %0;" : "+l"(a1[2 * m])     : "l"(h1), "l"(w.x));
            asm("fma.rn.f32x2 %0, %1, %2, %0;" : "+l"(a1[2 * m + 1]) : "l"(h1), "l"(w.y));
        }
    }
    __syncthreads();

#pragma unroll
    for (int j = 0; j < 16; j++) {
        float x0, y0, x1, y1;
        asm("mov.b64 {%0, %1}, %2;" : "=f"(x0), "=f"(y0) : "l"(a0[j]));
        asm("mov.b64 {%0, %1}, %2;" : "=f"(x1), "=f"(y1) : "l"(a1[j]));
        *(float2*)&sHT[(cbase + 2 * j) * HTS + r2]     = make_float2(x0, x1);
        *(float2*)&sHT[(cbase + 2 * j + 1) * HTS + r2] = make_float2(y0, y1);
    }
    __syncthreads();

    float* Obase = out + ((size_t)side * NROWS + base) * ND;
    for (int i = 0; i < 64; i++) {
        int e = i * 128 + t;
        int rr = e >> 6, k = e & 63;
        if (rr < rows) Obase[e] = sHT[k * HTS + rr];
    }
}

// ------------------------------------------------------------------
// Schedule (capture-safe fork/join):
//   main: transpose -> tdot0 -> attn0 -> [wait tdot1] attn1 -> mlp1 -> [wait mlp0]
//   s2  : [wait transpose] tdot1 ........ [wait attn0] mlp0
// Streams/events created per call, not destroyed (capture safety).
// ------------------------------------------------------------------
extern "C" void kernel_launch(void* const* d_in, const int* in_sizes, int n_in,
                              void* d_out, int out_size)
{
    const float* user_h = (const float*)d_in[0];
    const float* item_h = (const float*)d_in[1];
    const float* u_te   = (const float*)d_in[2];
    const float* i_te   = (const float*)d_in[3];
    const float* Wu1 = (const float*)d_in[4];
    const float* bu1 = (const float*)d_in[5];
    const float* Wu2 = (const float*)d_in[6];
    const float* bu2 = (const float*)d_in[7];
    const float* Wi1 = (const float*)d_in[8];
    const float* bi1 = (const float*)d_in[9];
    const float* Wi2 = (const float*)d_in[10];
    const float* bi2 = (const float*)d_in[11];
    const int* u_nbr = (const int*)d_in[12];
    const int* u_tim = (const int*)d_in[13];
    const int* i_nbr = (const int*)d_in[14];
    const int* i_tim = (const int*)d_in[15];
    float* out = (float*)d_out;

    cudaStream_t s2;
    cudaEvent_t evT, evT1, ev0, evM0;
    cudaStreamCreateWithFlags(&s2, cudaStreamNonBlocking);
    cudaEventCreateWithFlags(&evT,  cudaEventDisableTiming);
    cudaEventCreateWithFlags(&evT1, cudaEventDisableTiming);
    cudaEventCreateWithFlags(&ev0,  cudaEventDisableTiming);
    cudaEventCreateWithFlags(&evM0, cudaEventDisableTiming);

    const int GB = (NROWS + 127) / 128;

    te_transpose_kernel<<<2, 128>>>(u_te, i_te);
    cudaEventRecord(evT, 0);

    te_dot_kernel<<<GB, 128>>>(0, user_h, item_h);              // main

    cudaStreamWaitEvent(s2, evT, 0);
    te_dot_kernel<<<GB, 128, 0, s2>>>(1, user_h, item_h);       // overlaps attn0
    cudaEventRecord(evT1, s2);

    attn_kernel<<<NROWS, 64>>>(0, user_h, item_h,
                               u_nbr, u_tim, i_nbr, i_tim);     // main
    cudaEventRecord(ev0, 0);

    cudaStreamWaitEvent(s2, ev0, 0);
    mlp_kernel<<<GB, 128, 0, s2>>>(0, Wu1, bu1, Wu2, bu2, out); // overlaps attn1
    cudaEventRecord(evM0, s2);

    cudaStreamWaitEvent(0, evT1, 0);
    attn_kernel<<<NROWS, 64>>>(1, user_h, item_h,
                               u_nbr, u_tim, i_nbr, i_tim);     // main
    mlp_kernel<<<GB, 128>>>(1, Wi1, bi1, Wi2, bi2, out);        // main

    cudaStreamWaitEvent(0, evM0, 0);
}

// round 16
// speedup vs baseline: 1.0846x; 1.0846x over previous
#include <cuda_runtime.h>
#include <cstdint>

#define NL 50
#define ND 64
#define NROWS 50000
#define TOTROWS 100000

// 1 / sum_{m=0}^{49} e^{-m}
#define INV_C 0.63212055882855767841f

__device__ float g_H[(size_t)TOTROWS * ND];    // attention output scratch (25.6 MB)
__device__ float g_S[(size_t)TOTROWS * ND];    // te-dot scratch S[row][k] (25.6 MB)
__device__ float g_teT[2 * ND * ND];           // padded transposed te tables

// ------------------------------------------------------------------
// K-1: transpose te tables into padded [k][j] layout (j>=50 -> 0).
// ------------------------------------------------------------------
__global__ void te_transpose_kernel(const float* __restrict__ u_te,
                                    const float* __restrict__ i_te)
{
    const float* te = blockIdx.x ? i_te : u_te;
    float* out = g_teT + blockIdx.x * ND * ND;
    for (int idx = threadIdx.x; idx < ND * ND; idx += 128) {
        int k = idx >> 6, j = idx & 63;
        out[idx] = (j < NL) ? te[j * ND + k] : 0.f;
    }
}

#define HTS 130

// ------------------------------------------------------------------
// K0: S = dst_h @ te^T  (both sides via blockIdx.y).
// ------------------------------------------------------------------
__global__ __launch_bounds__(128) void te_dot_kernel(
    const float* __restrict__ user_h, const float* __restrict__ item_h)
{
    __shared__ __align__(16) float4 sW[ND * 16];    // 16 KB te_T
    __shared__ __align__(16) float sHT[ND * HTS];   // 33.3 KB k-major

    const int side = blockIdx.y;
    const float* src = side ? item_h : user_h;
    const int t = threadIdx.x;
    const int rp = t & 63, hf = t >> 6;

    for (int i = t; i < ND * 16; i += 128)
        sW[i] = ((const float4*)(g_teT + side * ND * ND))[i];

    const int base = blockIdx.x * 128;
    const int rows = min(128, NROWS - base);
    const float* Hbase = src + (size_t)base * ND;

    for (int i = 0; i < 64; i++) {
        int e = i * 128 + t;
        int rr = e >> 6, k = e & 63;
        sHT[k * HTS + rr] = (rr < rows) ? Hbase[e] : 0.f;
    }
    __syncthreads();

    const ulonglong2* Wp = (const ulonglong2*)sW;
    const int wbase = 8 * hf;
    const int cbase = 32 * hf;
    const int r2 = 2 * rp;

    unsigned long long a0[16], a1[16];
#pragma unroll
    for (int j = 0; j < 16; j++) { a0[j] = 0ull; a1[j] = 0ull; }
#pragma unroll 8
    for (int k = 0; k < ND; k++) {
        float2 h2 = *(const float2*)&sHT[k * HTS + r2];
        unsigned long long h0, h1;
        asm("mov.b64 %0, {%1, %1};" : "=l"(h0) : "f"(h2.x));
        asm("mov.b64 %0, {%1, %1};" : "=l"(h1) : "f"(h2.y));
#pragma unroll
        for (int m = 0; m < 8; m++) {
            ulonglong2 w = Wp[k * 16 + wbase + m];
            asm("fma.rn.f32x2 %0, %1, %2, %0;" : "+l"(a0[2 * m])     : "l"(h0), "l"(w.x));
            asm("fma.rn.f32x2 %0, %1, %2, %0;" : "+l"(a0[2 * m + 1]) : "l"(h0), "l"(w.y));
            asm("fma.rn.f32x2 %0, %1, %2, %0;" : "+l"(a1[2 * m])     : "l"(h1), "l"(w.x));
            asm("fma.rn.f32x2 %0, %1, %2, %0;" : "+l"(a1[2 * m + 1]) : "l"(h1), "l"(w.y));
        }
    }
    __syncthreads();

#pragma unroll
    for (int j = 0; j < 16; j++) {
        float x0, y0, x1, y1;
        asm("mov.b64 {%0, %1}, %2;" : "=f"(x0), "=f"(y0) : "l"(a0[j]));
        asm("mov.b64 {%0, %1}, %2;" : "=f"(x1), "=f"(y1) : "l"(a1[j]));
        *(float2*)&sHT[(cbase + 2 * j) * HTS + r2]     = make_float2(x0, x1);
        *(float2*)&sHT[(cbase + 2 * j + 1) * HTS + r2] = make_float2(y0, y1);
    }
    __syncthreads();

    float* Sbase = g_S + ((size_t)side * NROWS + base) * ND;
    for (int i = 0; i < 64; i++) {
        int e = i * 128 + t;
        int rr = e >> 6, k = e & 63;
        if (rr < rows) Sbase[e] = sHT[k * HTS + rr];
    }
}

// ------------------------------------------------------------------
// attn: one 64-thread block per destination row (both sides in grid).
// Rank via combined keys: key = (time << 6) | slot  (time < 100000
// -> fits in 31 bits, unique -> no tie handling needed).
// ------------------------------------------------------------------
__global__ __launch_bounds__(64) void attn_kernel(
    const float* __restrict__ user_h, const float* __restrict__ item_h,
    const int* __restrict__ u_nbr, const int* __restrict__ u_tim,
    const int* __restrict__ i_nbr, const int* __restrict__ i_tim)
{
    __shared__ __align__(16) int   s_key[52];
    __shared__ __align__(16) int   s_idx[52];      // pre-scaled by 16 (float4 units)
    __shared__ __align__(16) int   s_srt[52];
    __shared__ __align__(16) float s_pd[NL * 4];   // quad partials of <nbr,dst>
    __shared__ __align__(16) float s_S[52];
    __shared__ __align__(16) float s_g[52];
    __shared__ __align__(16) float s_alpha[52];
    __shared__             float s_wsum[2];
    __shared__ __align__(16) float4 s_red[32];

    const int row = blockIdx.x;
    const int t = threadIdx.x;
    const int lane = t & 31, wid = t >> 5;
    const int g = t >> 4, c = t & 15;
    const bool uside = row < NROWS;
    const int n = uside ? row : row - NROWS;
    const float*  dst  = (uside ? user_h : item_h) + (size_t)n * ND;
    const float4* src4 = (const float4*)(uside ? item_h : user_h);
    const int* nbr = (uside ? u_nbr : i_nbr) + (size_t)n * NL;
    const int* tim = (uside ? u_tim : i_tim) + (size_t)n * NL;
    const float* Srow = g_S + (size_t)row * ND;

    const float4 dstc = __ldg(&((const float4*)dst)[c]);

    if (t < NL) {
        s_idx[t] = __ldg(nbr + t) << 4;            // *16 float4 chunks
        s_key[t] = (__ldg(tim + t) << 6) | t;      // stable sort key
        s_S[t]   = __ldg(Srow + t);
    } else if (t < 52) {
        s_key[t]   = 0x7fffffff;   // pad: strictly greater than any real key
        s_idx[t]   = 0;
        s_g[t]     = -1e30f;       // pad for max loop
        s_alpha[t] = 0.f;          // pad for pass C
    }
    __syncthreads();               // bar1

    // --- gather: 16 consecutive lanes fetch one 256B neighbor row ---
    float4 v[13];
#pragma unroll
    for (int i = 0; i < 13; i++) {
        const int l = 4 * i + g;
        if (l < NL)
            v[i] = __ldg(&src4[(size_t)(s_idx[l] + c)]);
        else
            v[i] = make_float4(0.f, 0.f, 0.f, 0.f);
    }

    // --- rank via key counting (stable argsort) while gather in flight ---
    int ro = 0;
    if (t < NL) {
        const int kt = s_key[t];
        int r = 0;
#pragma unroll
        for (int i = 0; i < 13; i++) {
            int4 w = ((const int4*)s_key)[i];
            r += (w.x < kt) + (w.y < kt) + (w.z < kt) + (w.w < kt);
        }
        s_srt[r] = t;          // srt[r] = original index of rank-r time
        ro = NL - 1 - r;       // re_order
    }

    // --- score dots: 2 shfl levels -> quad partials -> smem ---
#pragma unroll
    for (int i = 0; i < 13; i++) {
        const int l = 4 * i + g;
        float d = v[i].x * dstc.x + v[i].y * dstc.y + v[i].z * dstc.z + v[i].w * dstc.w;
        d += __shfl_xor_sync(0xffffffffu, d, 1);
        d += __shfl_xor_sync(0xffffffffu, d, 2);
        if (((c & 3) == 0) && l < NL)
            s_pd[l * 4 + (c >> 2)] = d;
    }
    __syncthreads();   // bar2: partials + s_srt visible

    // --- e, rank prior, g ---
    if (t < NL) {
        float4 pd = ((const float4*)s_pd)[t];
        float dsum = (pd.x + pd.y) + (pd.z + pd.w);
        float e = (dsum + s_S[ro]) * 6.25f;                 // L/sqrt(D)
        float p = __expf((float)s_srt[t] - 49.0f) * INV_C;  // softmax of permutation
        s_g[t] = e * p;
    }
    __syncthreads();   // bar3

    // --- softmax max (redundant per-thread, ILP-friendly) ---
    float mx = -1e30f;
#pragma unroll
    for (int i = 0; i < 13; i++) {
        float4 g4 = ((const float4*)s_g)[i];
        mx = fmaxf(mx, fmaxf(fmaxf(g4.x, g4.y), fmaxf(g4.z, g4.w)));
    }
    if (t < NL) s_alpha[t] = __expf(s_g[t] - mx);
    __syncthreads();   // bar4

    // --- pass C: weighted column sums + folded alpha sum ---
    float4 pc = make_float4(0.f, 0.f, 0.f, 0.f);
    float psum = 0.f;
#pragma unroll
    for (int i = 0; i < 13; i++) {
        const float a = s_alpha[4 * i + g];   // pad zeros kill l>=50
        psum += a;
        pc.x += a * v[i].x; pc.y += a * v[i].y;
        pc.z += a * v[i].z; pc.w += a * v[i].w;
    }
    pc.x += __shfl_xor_sync(0xffffffffu, pc.x, 16);
    pc.y += __shfl_xor_sync(0xffffffffu, pc.y, 16);
    pc.z += __shfl_xor_sync(0xffffffffu, pc.z, 16);
    pc.w += __shfl_xor_sync(0xffffffffu, pc.w, 16);
    psum += __shfl_xor_sync(0xffffffffu, psum, 16);
    if (lane < 16) s_red[wid * 16 + c] = pc;
    if (lane == 0) s_wsum[wid] = psum;
    __syncthreads();   // bar5

    if (t < 16) {
        const float inv = 1.0f / (s_wsum[0] + s_wsum[1]);
        float4 a = s_red[t], b = s_red[16 + t];
        float4 h;
        h.x = (a.x + b.x) * inv;
        h.y = (a.y + b.y) * inv;
        h.z = (a.z + b.z) * inv;
        h.w = (a.w + b.w) * inv;
        ((float4*)(g_H + (size_t)row * ND))[t] = h;
    }
}

// ------------------------------------------------------------------
// mlp (proven best version): out = relu(H@W1+b1)@W2+b2
// ------------------------------------------------------------------
__global__ __launch_bounds__(128) void mlp_kernel(
    const float* __restrict__ W1u, const float* __restrict__ b1u,
    const float* __restrict__ W2u, const float* __restrict__ b2u,
    const float* __restrict__ W1i, const float* __restrict__ b1i,
    const float* __restrict__ W2i, const float* __restrict__ b2i,
    float* __restrict__ out)
{
    __shared__ __align__(16) float4 sW[ND * 16];    // 16 KB, W1 then W2
    __shared__ float sb1[ND];
    __shared__ float sb2[ND];
    __shared__ __align__(16) float sHT[ND * HTS];   // 33.3 KB, k-major

    const int side = blockIdx.y;
    const float* W1 = side ? W1i : W1u;
    const float* W2 = side ? W2i : W2u;
    const float* b1 = side ? b1i : b1u;
    const float* b2 = side ? b2i : b2u;
    const int t = threadIdx.x;
    const int rp = t & 63, hf = t >> 6;

    for (int i = t; i < ND * 16; i += 128)
        sW[i] = ((const float4*)W1)[i];
    if (t < ND) { sb1[t] = b1[t]; sb2[t] = b2[t]; }

    const int base = blockIdx.x * 128;
    const int rows = min(128, NROWS - base);
    const float* Hbase = g_H + ((size_t)side * NROWS + base) * ND;

    for (int i = 0; i < 64; i++) {
        int e = i * 128 + t;
        int rr = e >> 6, k = e & 63;
        sHT[k * HTS + rr] = (rr < rows) ? Hbase[e] : 0.f;
    }
    __syncthreads();

    const ulonglong2* Wp = (const ulonglong2*)sW;
    const int wbase = 8 * hf;
    const int cbase = 32 * hf;
    const int r2 = 2 * rp;

    // ---- layer 1 ----
    unsigned long long a0[16], a1[16];
#pragma unroll
    for (int j = 0; j < 16; j++) {
        unsigned long long b;
        asm("mov.b64 %0, {%1, %2};" : "=l"(b)
            : "f"(sb1[cbase + 2 * j]), "f"(sb1[cbase + 2 * j + 1]));
        a0[j] = b; a1[j] = b;
    }
#pragma unroll 8
    for (int k = 0; k < ND; k++) {
        float2 h2 = *(const float2*)&sHT[k * HTS + r2];
        unsigned long long h0, h1;
        asm("mov.b64 %0, {%1, %1};" : "=l"(h0) : "f"(h2.x));
        asm("mov.b64 %0, {%1, %1};" : "=l"(h1) : "f"(h2.y));
#pragma unroll
        for (int m = 0; m < 8; m++) {
            ulonglong2 w = Wp[k * 16 + wbase + m];
            asm("fma.rn.f32x2 %0, %1, %2, %0;" : "+l"(a0[2 * m])     : "l"(h0), "l"(w.x));
            asm("fma.rn.f32x2 %0, %1, %2, %0;" : "+l"(a0[2 * m + 1]) : "l"(h0), "l"(w.y));
            asm("fma.rn.f32x2 %0, %1, %2, %0;" : "+l"(a1[2 * m])     : "l"(h1), "l"(w.x));
            asm("fma.rn.f32x2 %0, %1, %2, %0;" : "+l"(a1[2 * m + 1]) : "l"(h1), "l"(w.y));
        }
    }
    __syncthreads();

#pragma unroll
    for (int j = 0; j < 16; j++) {
        float x0, y0, x1, y1;
        asm("mov.b64 {%0, %1}, %2;" : "=f"(x0), "=f"(y0) : "l"(a0[j]));
        asm("mov.b64 {%0, %1}, %2;" : "=f"(x1), "=f"(y1) : "l"(a1[j]));
        *(float2*)&sHT[(cbase + 2 * j) * HTS + r2] =
            make_float2(fmaxf(x0, 0.f), fmaxf(x1, 0.f));
        *(float2*)&sHT[(cbase + 2 * j + 1) * HTS + r2] =
            make_float2(fmaxf(y0, 0.f), fmaxf(y1, 0.f));
    }

    for (int i = t; i < ND * 16; i += 128)
        sW[i] = ((const float4*)W2)[i];
    __syncthreads();

    // ---- layer 2 ----
#pragma unroll
    for (int j = 0; j < 16; j++) {
        unsigned long long b;
        asm("mov.b64 %0, {%1, %2};" : "=l"(b)
            : "f"(sb2[cbase + 2 * j]), "f"(sb2[cbase + 2 * j + 1]));
        a0[j] = b; a1[j] = b;
    }
#pragma unroll 8
    for (int k = 0; k < ND; k++) {
        float2 h2 = *(const float2*)&sHT[k * HTS + r2];
        unsigned long long h0, h1;
        asm("mov.b64 %0, {%1, %1};" : "=l"(h0) : "f"(h2.x));
        asm("mov.b64 %0, {%1, %1};" : "=l"(h1) : "f"(h2.y));
#pragma unroll
        for (int m = 0; m < 8; m++) {
            ulonglong2 w = Wp[k * 16 + wbase + m];
            asm("fma.rn.f32x2 %0, %1, %2, %0;" : "+l"(a0[2 * m])     : "l"(h0), "l"(w.x));
            asm("fma.rn.f32x2 %0, %1, %2, %0;" : "+l"(a0[2 * m + 1]) : "l"(h0), "l"(w.y));
            asm("fma.rn.f32x2 %0, %1, %2, %0;" : "+l"(a1[2 * m])     : "l"(h1), "l"(w.x));
            asm("fma.rn.f32x2 %0, %1, %2, %0;" : "+l"(a1[2 * m + 1]) : "l"(h1), "l"(w.y));
        }
    }
    __syncthreads();

#pragma unroll
    for (int j = 0; j < 16; j++) {
        float x0, y0, x1, y1;
        asm("mov.b64 {%0, %1}, %2;" : "=f"(x0), "=f"(y0) : "l"(a0[j]));
        asm("mov.b64 {%0, %1}, %2;" : "=f"(x1), "=f"(y1) : "l"(a1[j]));
        *(float2*)&sHT[(cbase + 2 * j) * HTS + r2]     = make_float2(x0, x1);
        *(float2*)&sHT[(cbase + 2 * j + 1) * HTS + r2] = make_float2(y0, y1);
    }
    __syncthreads();

    float* Obase = out + ((size_t)side * NROWS + base) * ND;
    for (int i = 0; i < 64; i++) {
        int e = i * 128 + t;
        int rr = e >> 6, k = e & 63;
        if (rr < rows) Obase[e] = sHT[k * HTS + rr];
    }
}

// ------------------------------------------------------------------
extern "C" void kernel_launch(void* const* d_in, const int* in_sizes, int n_in,
                              void* d_out, int out_size)
{
    const float* user_h = (const float*)d_in[0];
    const float* item_h = (const float*)d_in[1];
    const float* u_te   = (const float*)d_in[2];
    const float* i_te   = (const float*)d_in[3];
    const float* Wu1 = (const float*)d_in[4];
    const float* bu1 = (const float*)d_in[5];
    const float* Wu2 = (const float*)d_in[6];
    const float* bu2 = (const float*)d_in[7];
    const float* Wi1 = (const float*)d_in[8];
    const float* bi1 = (const float*)d_in[9];
    const float* Wi2 = (const float*)d_in[10];
    const float* bi2 = (const float*)d_in[11];
    const int* u_nbr = (const int*)d_in[12];
    const int* u_tim = (const int*)d_in[13];
    const int* i_nbr = (const int*)d_in[14];
    const int* i_tim = (const int*)d_in[15];
    float* out = (float*)d_out;

    te_transpose_kernel<<<2, 128>>>(u_te, i_te);
    te_dot_kernel<<<dim3((NROWS + 127) / 128, 2), 128>>>(user_h, item_h);
    attn_kernel<<<TOTROWS, 64>>>(user_h, item_h,
                                 u_nbr, u_tim, i_nbr, i_tim);
    mlp_kernel<<<dim3((NROWS + 127) / 128, 2), 128>>>(Wu1, bu1, Wu2, bu2,
                                                      Wi1, bi1, Wi2, bi2, out);
}

// round 17
// speedup vs baseline: 1.1033x; 1.0172x over previous
#include <cuda_runtime.h>
#include <cstdint>

#define NL 50
#define ND 64
#define NROWS 50000
#define TOTROWS 100000

// 1 / sum_{m=0}^{49} e^{-m}
#define INV_C 0.63212055882855767841f

__device__ float g_H[(size_t)TOTROWS * ND];    // attention output scratch (25.6 MB)
__device__ float g_S[(size_t)TOTROWS * ND];    // te-dot scratch S[row][k] (25.6 MB)
__device__ float g_teT[2 * ND * ND];           // padded transposed te tables

// ------------------------------------------------------------------
// K-1: transpose te tables into padded [k][j] layout (j>=50 -> 0).
// ------------------------------------------------------------------
__global__ void te_transpose_kernel(const float* __restrict__ u_te,
                                    const float* __restrict__ i_te)
{
    const float* te = blockIdx.x ? i_te : u_te;
    float* out = g_teT + blockIdx.x * ND * ND;
    for (int idx = threadIdx.x; idx < ND * ND; idx += 128) {
        int k = idx >> 6, j = idx & 63;
        out[idx] = (j < NL) ? te[j * ND + k] : 0.f;
    }
}

#define HTS 130

// ------------------------------------------------------------------
// K0: S = dst_h @ te^T.  4 rows x 16 cols per thread:
// thread (rp = t&31 -> rows 4rp..4rp+3, q = t>>5 -> cols 16q..16q+15).
// Per k: 2 LDS.64 (h) + 4 LDS.128 (w) feed 32 f32x2 FMAs.
// ------------------------------------------------------------------
__global__ __launch_bounds__(128) void te_dot_kernel(
    const float* __restrict__ user_h, const float* __restrict__ item_h)
{
    __shared__ __align__(16) float4 sW[ND * 16];    // 16 KB te_T
    __shared__ __align__(16) float sHT[ND * HTS];   // 33.3 KB k-major

    const int side = blockIdx.y;
    const float* src = side ? item_h : user_h;
    const int t = threadIdx.x;
    const int rp = t & 31, q = t >> 5;
    const int r4 = 4 * rp;
    const int wb = 4 * q;          // my 4 ulonglong2 per weight row
    const int cbase = 16 * q;      // my output-column base

    for (int i = t; i < ND * 16; i += 128)
        sW[i] = ((const float4*)(g_teT + side * ND * ND))[i];

    const int base = blockIdx.x * 128;
    const int rows = min(128, NROWS - base);
    const float* Hbase = src + (size_t)base * ND;

    for (int i = 0; i < 64; i++) {
        int e = i * 128 + t;
        int rr = e >> 6, k = e & 63;
        sHT[k * HTS + rr] = (rr < rows) ? Hbase[e] : 0.f;
    }
    __syncthreads();

    const ulonglong2* Wp = (const ulonglong2*)sW;

    unsigned long long a[32];      // a[r*8 + j]: row r4+r, cols cbase+2j,2j+1
#pragma unroll
    for (int j = 0; j < 32; j++) a[j] = 0ull;
#pragma unroll 8
    for (int k = 0; k < ND; k++) {
        const float* hp = &sHT[k * HTS + r4];
        float2 hA = *(const float2*)hp;
        float2 hB = *(const float2*)(hp + 2);
        unsigned long long h0, h1, h2, h3;
        asm("mov.b64 %0, {%1, %1};" : "=l"(h0) : "f"(hA.x));
        asm("mov.b64 %0, {%1, %1};" : "=l"(h1) : "f"(hA.y));
        asm("mov.b64 %0, {%1, %1};" : "=l"(h2) : "f"(hB.x));
        asm("mov.b64 %0, {%1, %1};" : "=l"(h3) : "f"(hB.y));
#pragma unroll
        for (int m = 0; m < 4; m++) {
            ulonglong2 w = Wp[k * 16 + wb + m];
            asm("fma.rn.f32x2 %0, %1, %2, %0;" : "+l"(a[     2*m    ]) : "l"(h0), "l"(w.x));
            asm("fma.rn.f32x2 %0, %1, %2, %0;" : "+l"(a[     2*m + 1]) : "l"(h0), "l"(w.y));
            asm("fma.rn.f32x2 %0, %1, %2, %0;" : "+l"(a[ 8 + 2*m    ]) : "l"(h1), "l"(w.x));
            asm("fma.rn.f32x2 %0, %1, %2, %0;" : "+l"(a[ 8 + 2*m + 1]) : "l"(h1), "l"(w.y));
            asm("fma.rn.f32x2 %0, %1, %2, %0;" : "+l"(a[16 + 2*m    ]) : "l"(h2), "l"(w.x));
            asm("fma.rn.f32x2 %0, %1, %2, %0;" : "+l"(a[16 + 2*m + 1]) : "l"(h2), "l"(w.y));
            asm("fma.rn.f32x2 %0, %1, %2, %0;" : "+l"(a[24 + 2*m    ]) : "l"(h3), "l"(w.x));
            asm("fma.rn.f32x2 %0, %1, %2, %0;" : "+l"(a[24 + 2*m + 1]) : "l"(h3), "l"(w.y));
        }
    }
    __syncthreads();

    // write S values back to sHT columns (no relu)
#pragma unroll
    for (int j = 0; j < 8; j++) {
        float x0, y0, x1, y1, x2, y2, x3, y3;
        asm("mov.b64 {%0, %1}, %2;" : "=f"(x0), "=f"(y0) : "l"(a[     j]));
        asm("mov.b64 {%0, %1}, %2;" : "=f"(x1), "=f"(y1) : "l"(a[ 8 + j]));
        asm("mov.b64 {%0, %1}, %2;" : "=f"(x2), "=f"(y2) : "l"(a[16 + j]));
        asm("mov.b64 {%0, %1}, %2;" : "=f"(x3), "=f"(y3) : "l"(a[24 + j]));
        const int c0 = cbase + 2 * j, c1 = c0 + 1;
        *(float2*)&sHT[c0 * HTS + r4]     = make_float2(x0, x1);
        *(float2*)&sHT[c0 * HTS + r4 + 2] = make_float2(x2, x3);
        *(float2*)&sHT[c1 * HTS + r4]     = make_float2(y0, y1);
        *(float2*)&sHT[c1 * HTS + r4 + 2] = make_float2(y2, y3);
    }
    __syncthreads();

    float* Sbase = g_S + ((size_t)side * NROWS + base) * ND;
    for (int i = 0; i < 64; i++) {
        int e = i * 128 + t;
        int rr = e >> 6, k = e & 63;
        if (rr < rows) Sbase[e] = sHT[k * HTS + rr];
    }
}

// ------------------------------------------------------------------
// attn (R16 winner, unchanged): one 64-thread block per destination row.
// ------------------------------------------------------------------
__global__ __launch_bounds__(64) void attn_kernel(
    const float* __restrict__ user_h, const float* __restrict__ item_h,
    const int* __restrict__ u_nbr, const int* __restrict__ u_tim,
    const int* __restrict__ i_nbr, const int* __restrict__ i_tim)
{
    __shared__ __align__(16) int   s_key[52];
    __shared__ __align__(16) int   s_idx[52];      // pre-scaled by 16
    __shared__ __align__(16) int   s_srt[52];
    __shared__ __align__(16) float s_pd[NL * 4];
    __shared__ __align__(16) float s_S[52];
    __shared__ __align__(16) float s_g[52];
    __shared__ __align__(16) float s_alpha[52];
    __shared__             float s_wsum[2];
    __shared__ __align__(16) float4 s_red[32];

    const int row = blockIdx.x;
    const int t = threadIdx.x;
    const int lane = t & 31, wid = t >> 5;
    const int g = t >> 4, c = t & 15;
    const bool uside = row < NROWS;
    const int n = uside ? row : row - NROWS;
    const float*  dst  = (uside ? user_h : item_h) + (size_t)n * ND;
    const float4* src4 = (const float4*)(uside ? item_h : user_h);
    const int* nbr = (uside ? u_nbr : i_nbr) + (size_t)n * NL;
    const int* tim = (uside ? u_tim : i_tim) + (size_t)n * NL;
    const float* Srow = g_S + (size_t)row * ND;

    const float4 dstc = __ldg(&((const float4*)dst)[c]);

    if (t < NL) {
        s_idx[t] = __ldg(nbr + t) << 4;
        s_key[t] = (__ldg(tim + t) << 6) | t;
        s_S[t]   = __ldg(Srow + t);
    } else if (t < 52) {
        s_key[t]   = 0x7fffffff;
        s_idx[t]   = 0;
        s_g[t]     = -1e30f;
        s_alpha[t] = 0.f;
    }
    __syncthreads();

    float4 v[13];
#pragma unroll
    for (int i = 0; i < 13; i++) {
        const int l = 4 * i + g;
        if (l < NL)
            v[i] = __ldg(&src4[(size_t)(s_idx[l] + c)]);
        else
            v[i] = make_float4(0.f, 0.f, 0.f, 0.f);
    }

    int ro = 0;
    if (t < NL) {
        const int kt = s_key[t];
        int r = 0;
#pragma unroll
        for (int i = 0; i < 13; i++) {
            int4 w = ((const int4*)s_key)[i];
            r += (w.x < kt) + (w.y < kt) + (w.z < kt) + (w.w < kt);
        }
        s_srt[r] = t;
        ro = NL - 1 - r;
    }

#pragma unroll
    for (int i = 0; i < 13; i++) {
        const int l = 4 * i + g;
        float d = v[i].x * dstc.x + v[i].y * dstc.y + v[i].z * dstc.z + v[i].w * dstc.w;
        d += __shfl_xor_sync(0xffffffffu, d, 1);
        d += __shfl_xor_sync(0xffffffffu, d, 2);
        if (((c & 3) == 0) && l < NL)
            s_pd[l * 4 + (c >> 2)] = d;
    }
    __syncthreads();

    if (t < NL) {
        float4 pd = ((const float4*)s_pd)[t];
        float dsum = (pd.x + pd.y) + (pd.z + pd.w);
        float e = (dsum + s_S[ro]) * 6.25f;
        float p = __expf((float)s_srt[t] - 49.0f) * INV_C;
        s_g[t] = e * p;
    }
    __syncthreads();

    float mx = -1e30f;
#pragma unroll
    for (int i = 0; i < 13; i++) {
        float4 g4 = ((const float4*)s_g)[i];
        mx = fmaxf(mx, fmaxf(fmaxf(g4.x, g4.y), fmaxf(g4.z, g4.w)));
    }
    if (t < NL) s_alpha[t] = __expf(s_g[t] - mx);
    __syncthreads();

    float4 pc = make_float4(0.f, 0.f, 0.f, 0.f);
    float psum = 0.f;
#pragma unroll
    for (int i = 0; i < 13; i++) {
        const float a = s_alpha[4 * i + g];
        psum += a;
        pc.x += a * v[i].x; pc.y += a * v[i].y;
        pc.z += a * v[i].z; pc.w += a * v[i].w;
    }
    pc.x += __shfl_xor_sync(0xffffffffu, pc.x, 16);
    pc.y += __shfl_xor_sync(0xffffffffu, pc.y, 16);
    pc.z += __shfl_xor_sync(0xffffffffu, pc.z, 16);
    pc.w += __shfl_xor_sync(0xffffffffu, pc.w, 16);
    psum += __shfl_xor_sync(0xffffffffu, psum, 16);
    if (lane < 16) s_red[wid * 16 + c] = pc;
    if (lane == 0) s_wsum[wid] = psum;
    __syncthreads();

    if (t < 16) {
        const float inv = 1.0f / (s_wsum[0] + s_wsum[1]);
        float4 a = s_red[t], b = s_red[16 + t];
        float4 h;
        h.x = (a.x + b.x) * inv;
        h.y = (a.y + b.y) * inv;
        h.z = (a.z + b.z) * inv;
        h.w = (a.w + b.w) * inv;
        ((float4*)(g_H + (size_t)row * ND))[t] = h;
    }
}

// ------------------------------------------------------------------
// mlp: out = relu(H@W1+b1)@W2+b2.  4 rows x 16 cols per thread.
// ------------------------------------------------------------------
__global__ __launch_bounds__(128) void mlp_kernel(
    const float* __restrict__ W1u, const float* __restrict__ b1u,
    const float* __restrict__ W2u, const float* __restrict__ b2u,
    const float* __restrict__ W1i, const float* __restrict__ b1i,
    const float* __restrict__ W2i, const float* __restrict__ b2i,
    float* __restrict__ out)
{
    __shared__ __align__(16) float4 sW[ND * 16];    // 16 KB, W1 then W2
    __shared__ float sb1[ND];
    __shared__ float sb2[ND];
    __shared__ __align__(16) float sHT[ND * HTS];   // 33.3 KB, k-major

    const int side = blockIdx.y;
    const float* W1 = side ? W1i : W1u;
    const float* W2 = side ? W2i : W2u;
    const float* b1 = side ? b1i : b1u;
    const float* b2 = side ? b2i : b2u;
    const int t = threadIdx.x;
    const int rp = t & 31, q = t >> 5;
    const int r4 = 4 * rp;
    const int wb = 4 * q;
    const int cbase = 16 * q;

    for (int i = t; i < ND * 16; i += 128)
        sW[i] = ((const float4*)W1)[i];
    if (t < ND) { sb1[t] = b1[t]; sb2[t] = b2[t]; }

    const int base = blockIdx.x * 128;
    const int rows = min(128, NROWS - base);
    const float* Hbase = g_H + ((size_t)side * NROWS + base) * ND;

    for (int i = 0; i < 64; i++) {
        int e = i * 128 + t;
        int rr = e >> 6, k = e & 63;
        sHT[k * HTS + rr] = (rr < rows) ? Hbase[e] : 0.f;
    }
    __syncthreads();

    const ulonglong2* Wp = (const ulonglong2*)sW;

    // ---- layer 1 ----
    unsigned long long a[32];      // a[r*8 + j]: row r4+r, cols cbase+2j,2j+1
#pragma unroll
    for (int j = 0; j < 8; j++) {
        unsigned long long b;
        asm("mov.b64 %0, {%1, %2};" : "=l"(b)
            : "f"(sb1[cbase + 2 * j]), "f"(sb1[cbase + 2 * j + 1]));
        a[j] = b; a[8 + j] = b; a[16 + j] = b; a[24 + j] = b;
    }
#pragma unroll 8
    for (int k = 0; k < ND; k++) {
        const float* hp = &sHT[k * HTS + r4];
        float2 hA = *(const float2*)hp;
        float2 hB = *(const float2*)(hp + 2);
        unsigned long long h0, h1, h2, h3;
        asm("mov.b64 %0, {%1, %1};" : "=l"(h0) : "f"(hA.x));
        asm("mov.b64 %0, {%1, %1};" : "=l"(h1) : "f"(hA.y));
        asm("mov.b64 %0, {%1, %1};" : "=l"(h2) : "f"(hB.x));
        asm("mov.b64 %0, {%1, %1};" : "=l"(h3) : "f"(hB.y));
#pragma unroll
        for (int m = 0; m < 4; m++) {
            ulonglong2 w = Wp[k * 16 + wb + m];
            asm("fma.rn.f32x2 %0, %1, %2, %0;" : "+l"(a[     2*m    ]) : "l"(h0), "l"(w.x));
            asm("fma.rn.f32x2 %0, %1, %2, %0;" : "+l"(a[     2*m + 1]) : "l"(h0), "l"(w.y));
            asm("fma.rn.f32x2 %0, %1, %2, %0;" : "+l"(a[ 8 + 2*m    ]) : "l"(h1), "l"(w.x));
            asm("fma.rn.f32x2 %0, %1, %2, %0;" : "+l"(a[ 8 + 2*m + 1]) : "l"(h1), "l"(w.y));
            asm("fma.rn.f32x2 %0, %1, %2, %0;" : "+l"(a[16 + 2*m    ]) : "l"(h2), "l"(w.x));
            asm("fma.rn.f32x2 %0, %1, %2, %0;" : "+l"(a[16 + 2*m + 1]) : "l"(h2), "l"(w.y));
            asm("fma.rn.f32x2 %0, %1, %2, %0;" : "+l"(a[24 + 2*m    ]) : "l"(h3), "l"(w.x));
            asm("fma.rn.f32x2 %0, %1, %2, %0;" : "+l"(a[24 + 2*m + 1]) : "l"(h3), "l"(w.y));
        }
    }
    __syncthreads();   // done reading sW (W1) and sHT (layer-1 inputs)

    // relu -> sHT columns
#pragma unroll
    for (int j = 0; j < 8; j++) {
        float x0, y0, x1, y1, x2, y2, x3, y3;
        asm("mov.b64 {%0, %1}, %2;" : "=f"(x0), "=f"(y0) : "l"(a[     j]));
        asm("mov.b64 {%0, %1}, %2;" : "=f"(x1), "=f"(y1) : "l"(a[ 8 + j]));
        asm("mov.b64 {%0, %1}, %2;" : "=f"(x2), "=f"(y2) : "l"(a[16 + j]));
        asm("mov.b64 {%0, %1}, %2;" : "=f"(x3), "=f"(y3) : "l"(a[24 + j]));
        const int c0 = cbase + 2 * j, c1 = c0 + 1;
        *(float2*)&sHT[c0 * HTS + r4]     = make_float2(fmaxf(x0, 0.f), fmaxf(x1, 0.f));
        *(float2*)&sHT[c0 * HTS + r4 + 2] = make_float2(fmaxf(x2, 0.f), fmaxf(x3, 0.f));
        *(float2*)&sHT[c1 * HTS + r4]     = make_float2(fmaxf(y0, 0.f), fmaxf(y1, 0.f));
        *(float2*)&sHT[c1 * HTS + r4 + 2] = make_float2(fmaxf(y2, 0.f), fmaxf(y3, 0.f));
    }

    // reload weight buffer with W2 (L1/L2-hot)
    for (int i = t; i < ND * 16; i += 128)
        sW[i] = ((const float4*)W2)[i];
    __syncthreads();   // W2 + all relu writes visible

    // ---- layer 2 ----
#pragma unroll
    for (int j = 0; j < 8; j++) {
        unsigned long long b;
        asm("mov.b64 %0, {%1, %2};" : "=l"(b)
            : "f"(sb2[cbase + 2 * j]), "f"(sb2[cbase + 2 * j + 1]));
        a[j] = b; a[8 + j] = b; a[16 + j] = b; a[24 + j] = b;
    }
#pragma unroll 8
    for (int k = 0; k < ND; k++) {
        const float* hp = &sHT[k * HTS + r4];
        float2 hA = *(const float2*)hp;
        float2 hB = *(const float2*)(hp + 2);
        unsigned long long h0, h1, h2, h3;
        asm("mov.b64 %0, {%1, %1};" : "=l"(h0) : "f"(hA.x));
        asm("mov.b64 %0, {%1, %1};" : "=l"(h1) : "f"(hA.y));
        asm("mov.b64 %0, {%1, %1};" : "=l"(h2) : "f"(hB.x));
        asm("mov.b64 %0, {%1, %1};" : "=l"(h3) : "f"(hB.y));
#pragma unroll
        for (int m = 0; m < 4; m++) {
            ulonglong2 w = Wp[k * 16 + wb + m];
            asm("fma.rn.f32x2 %0, %1, %2, %0;" : "+l"(a[     2*m    ]) : "l"(h0), "l"(w.x));
            asm("fma.rn.f32x2 %0, %1, %2, %0;" : "+l"(a[     2*m + 1]) : "l"(h0), "l"(w.y));
            asm("fma.rn.f32x2 %0, %1, %2, %0;" : "+l"(a[ 8 + 2*m    ]) : "l"(h1), "l"(w.x));
            asm("fma.rn.f32x2 %0, %1, %2, %0;" : "+l"(a[ 8 + 2*m + 1]) : "l"(h1), "l"(w.y));
            asm("fma.rn.f32x2 %0, %1, %2, %0;" : "+l"(a[16 + 2*m    ]) : "l"(h2), "l"(w.x));
            asm("fma.rn.f32x2 %0, %1, %2, %0;" : "+l"(a[16 + 2*m + 1]) : "l"(h2), "l"(w.y));
            asm("fma.rn.f32x2 %0, %1, %2, %0;" : "+l"(a[24 + 2*m    ]) : "l"(h3), "l"(w.x));
            asm("fma.rn.f32x2 %0, %1, %2, %0;" : "+l"(a[24 + 2*m + 1]) : "l"(h3), "l"(w.y));
        }
    }
    __syncthreads();   // done reading sHT (layer-2 inputs)

    // write o2 back, then cooperative coalesced store
#pragma unroll
    for (int j = 0; j < 8; j++) {
        float x0, y0, x1, y1, x2, y2, x3, y3;
        asm("mov.b64 {%0, %1}, %2;" : "=f"(x0), "=f"(y0) : "l"(a[     j]));
        asm("mov.b64 {%0, %1}, %2;" : "=f"(x1), "=f"(y1) : "l"(a[ 8 + j]));
        asm("mov.b64 {%0, %1}, %2;" : "=f"(x2), "=f"(y2) : "l"(a[16 + j]));
        asm("mov.b64 {%0, %1}, %2;" : "=f"(x3), "=f"(y3) : "l"(a[24 + j]));
        const int c0 = cbase + 2 * j, c1 = c0 + 1;
        *(float2*)&sHT[c0 * HTS + r4]     = make_float2(x0, x1);
        *(float2*)&sHT[c0 * HTS + r4 + 2] = make_float2(x2, x3);
        *(float2*)&sHT[c1 * HTS + r4]     = make_float2(y0, y1);
        *(float2*)&sHT[c1 * HTS + r4 + 2] = make_float2(y2, y3);
    }
    __syncthreads();

    float* Obase = out + ((size_t)side * NROWS + base) * ND;
    for (int i = 0; i < 64; i++) {
        int e = i * 128 + t;
        int rr = e >> 6, k = e & 63;
        if (rr < rows) Obase[e] = sHT[k * HTS + rr];
    }
}

// ------------------------------------------------------------------
extern "C" void kernel_launch(void* const* d_in, const int* in_sizes, int n_in,
                              void* d_out, int out_size)
{
    const float* user_h = (const float*)d_in[0];
    const float* item_h = (const float*)d_in[1];
    const float* u_te   = (const float*)d_in[2];
    const float* i_te   = (const float*)d_in[3];
    const float* Wu1 = (const float*)d_in[4];
    const float* bu1 = (const float*)d_in[5];
    const float* Wu2 = (const float*)d_in[6];
    const float* bu2 = (const float*)d_in[7];
    const float* Wi1 = (const float*)d_in[8];
    const float* bi1 = (const float*)d_in[9];
    const float* Wi2 = (const float*)d_in[10];
    const float* bi2 = (const float*)d_in[11];
    const int* u_nbr = (const int*)d_in[12];
    const int* u_tim = (const int*)d_in[13];
    const int* i_nbr = (const int*)d_in[14];
    const int* i_tim = (const int*)d_in[15];
    float* out = (float*)d_out;

    te_transpose_kernel<<<2, 128>>>(u_te, i_te);
    te_dot_kernel<<<dim3((NROWS + 127) / 128, 2), 128>>>(user_h, item_h);
    attn_kernel<<<TOTROWS, 64>>>(user_h, item_h,
                                 u_nbr, u_tim, i_nbr, i_tim);
    mlp_kernel<<<dim3((NROWS + 127) / 128, 2), 128>>>(Wu1, bu1, Wu2, bu2,
                                                      Wi1, bi1, Wi2, bi2, out);
}